// round 9
// baseline (speedup 1.0000x reference)
#include <cuda_runtime.h>
#include <cuda_fp16.h>
#include <cuda_bf16.h>
#include <math.h>

#define NNODES 100000
#define NEDGES 3200000
#define NFEAT  256
#define NHID   128
#define NCLASS 40

// ---------------- scratch (static device globals; no allocs) ----------------
__device__ __half         g_sa[(size_t)NNODES * NHID];   // self proj, layer1
__device__ __half         g_za[(size_t)NNODES * NHID];   // neigh proj, layer1
__device__ __half         g_sb[(size_t)NNODES * NHID];   // self proj, layer2
__device__ __half         g_zb[(size_t)NNODES * NHID];   // neigh proj, layer2
__device__ __nv_bfloat16  g_hb[(size_t)NNODES * NHID];   // layer output bf16
__device__ __nv_bfloat16  g_xb[(size_t)NNODES * NFEAT];  // x in bf16
__device__ __nv_bfloat16  g_w1b[NHID * 2 * NFEAT];
__device__ __nv_bfloat16  g_w2b[NHID * 2 * NHID];
__device__ int            g_deg[NNODES];
__device__ int            g_rowptr[NNODES + 1];
__device__ int            g_cursor[NNODES];
__device__ int            g_col[NEDGES];

// ---------------- helpers ----------------
__device__ __forceinline__ unsigned pack_bf16x2(float lo, float hi) {
    unsigned u;
    asm("cvt.rn.bf16x2.f32 %0, %1, %2;" : "=r"(u) : "f"(hi), "f"(lo));
    return u;
}
__device__ __forceinline__ unsigned f2tf32(float v) {
    unsigned u;
    asm("cvt.rna.tf32.f32 %0, %1;" : "=r"(u) : "f"(v));
    return u;
}
__device__ __forceinline__ void mma_bf16(float* c, const unsigned* a,
                                         unsigned b0, unsigned b1) {
    asm volatile(
        "mma.sync.aligned.m16n8k16.row.col.f32.bf16.bf16.f32 "
        "{%0,%1,%2,%3}, {%4,%5,%6,%7}, {%8,%9}, {%0,%1,%2,%3};"
        : "+f"(c[0]), "+f"(c[1]), "+f"(c[2]), "+f"(c[3])
        : "r"(a[0]), "r"(a[1]), "r"(a[2]), "r"(a[3]), "r"(b0), "r"(b1));
}
__device__ __forceinline__ void mma_tf32(float* c, const unsigned* a,
                                         unsigned b0, unsigned b1) {
    asm volatile(
        "mma.sync.aligned.m16n8k8.row.col.f32.tf32.tf32.f32 "
        "{%0,%1,%2,%3}, {%4,%5,%6,%7}, {%8,%9}, {%0,%1,%2,%3};"
        : "+f"(c[0]), "+f"(c[1]), "+f"(c[2]), "+f"(c[3])
        : "r"(a[0]), "r"(a[1]), "r"(a[2]), "r"(a[3]), "r"(b0), "r"(b1));
}
__device__ __forceinline__ unsigned s2u(const void* p) {
    return (unsigned)__cvta_generic_to_shared(p);
}
__device__ __forceinline__ void cp16(unsigned dst, const void* src, bool pred) {
    int sz = pred ? 16 : 0;
    asm volatile("cp.async.cg.shared.global [%0], [%1], 16, %2;"
                 :: "r"(dst), "l"(src), "r"(sz));
}
#define CP_COMMIT() asm volatile("cp.async.commit_group;")
#define CP_WAIT1()  asm volatile("cp.async.wait_group 1;")
#define CP_WAIT0()  asm volatile("cp.async.wait_group 0;")

// ---------------- fp32 -> bf16 convert ----------------
__global__ void k_cvt(const float* __restrict__ in, __nv_bfloat16* __restrict__ out,
                      int n4) {
    int i = blockIdx.x * blockDim.x + threadIdx.x;
    if (i < n4) {
        float4 v = ((const float4*)in)[i];
        ((uint2*)out)[i] = make_uint2(pack_bf16x2(v.x, v.y), pack_bf16x2(v.z, v.w));
    }
}

// ---------------- CSR build (4 edges / thread) ----------------
__global__ void k_count(const int* __restrict__ rows, int* __restrict__ deg) {
    int i = blockIdx.x * blockDim.x + threadIdx.x;
    if (i < NEDGES / 4) {
        int4 r = ((const int4*)rows)[i];
        atomicAdd(&deg[r.x], 1);
        atomicAdd(&deg[r.y], 1);
        atomicAdd(&deg[r.z], 1);
        atomicAdd(&deg[r.w], 1);
    }
}

__global__ void k_scan(const int* __restrict__ deg, int* __restrict__ rp,
                       int* __restrict__ cur) {
    __shared__ int wsum[32];
    __shared__ int carry;
    int tid = threadIdx.x, lane = tid & 31, wid = tid >> 5;
    if (tid == 0) carry = 0;
    __syncthreads();
    for (int base = 0; base < NNODES; base += 1024) {
        int i = base + tid;
        int v = (i < NNODES) ? deg[i] : 0;
        int x = v;
        #pragma unroll
        for (int d = 1; d < 32; d <<= 1) {
            int y = __shfl_up_sync(0xffffffffu, x, d);
            if (lane >= d) x += y;
        }
        if (lane == 31) wsum[wid] = x;
        __syncthreads();
        if (wid == 0) {
            int s = wsum[lane];
            #pragma unroll
            for (int d = 1; d < 32; d <<= 1) {
                int y = __shfl_up_sync(0xffffffffu, s, d);
                if (lane >= d) s += y;
            }
            wsum[lane] = s;
        }
        __syncthreads();
        int off  = carry + (wid ? wsum[wid - 1] : 0);
        int excl = off + x - v;
        if (i < NNODES) { rp[i] = excl; cur[i] = excl; }
        int tot = wsum[31];
        __syncthreads();
        if (tid == 0) carry += tot;
        __syncthreads();
    }
    if (tid == 0) rp[NNODES] = carry;
}

__global__ void k_fill(const int* __restrict__ rows, const int* __restrict__ cols,
                       int* __restrict__ cur, int* __restrict__ col) {
    int i = blockIdx.x * blockDim.x + threadIdx.x;
    if (i < NEDGES / 4) {
        int4 r = ((const int4*)rows)[i];
        int4 c = ((const int4*)cols)[i];
        col[atomicAdd(&cur[r.x], 1)] = c.x;
        col[atomicAdd(&cur[r.y], 1)] = c.y;
        col[atomicAdd(&cur[r.z], 1)] = c.z;
        col[atomicAdd(&cur[r.w], 1)] = c.w;
    }
}

// ---------------- pipelined bf16 GEMM (both outputs fp16) ----------------
#define PITCH 80
__global__ __launch_bounds__(256) void k_gemm_bf16(
    const __nv_bfloat16* __restrict__ A, int K,
    const __nv_bfloat16* __restrict__ W,
    __half* __restrict__ Csh, __half* __restrict__ Czh, int rowbase)
{
    __shared__ __align__(16) unsigned char smA[2][128 * PITCH];
    __shared__ __align__(16) unsigned char smB[2][128 * PITCH];
    const int tid = threadIdx.x, lane = tid & 31, wid = tid >> 5;
    const int warpM = wid & 3, warpN = wid >> 2;
    const int row0 = rowbase + blockIdx.x * 128;
    const int ldw = 2 * K;
    const __nv_bfloat16* Wb = W + (size_t)blockIdx.y * K;
    __half* C = blockIdx.y ? Czh : Csh;
    const int NT = K >> 5;

    const int lr0 = tid >> 2, lc0 = tid & 3;
    const int lr1 = (tid + 256) >> 2, lc1 = lc0;
    const bool p0 = (row0 + lr0) < NNODES;
    const bool p1 = (row0 + lr1) < NNODES;

    float acc[2][8][4];
    #pragma unroll
    for (int mi = 0; mi < 2; mi++)
        #pragma unroll
        for (int ni = 0; ni < 8; ni++)
            #pragma unroll
            for (int q = 0; q < 4; q++) acc[mi][ni][q] = 0.f;

    {
        cp16(s2u(smA[0] + lr0 * PITCH + lc0 * 16),
             A + (size_t)(row0 + lr0) * K + lc0 * 8, p0);
        cp16(s2u(smA[0] + lr1 * PITCH + lc1 * 16),
             A + (size_t)(row0 + lr1) * K + lc1 * 8, p1);
        cp16(s2u(smB[0] + lr0 * PITCH + lc0 * 16),
             Wb + (size_t)lr0 * ldw + lc0 * 8, true);
        cp16(s2u(smB[0] + lr1 * PITCH + lc1 * 16),
             Wb + (size_t)lr1 * ldw + lc1 * 8, true);
        CP_COMMIT();
    }

    for (int kt = 0; kt < NT; kt++) {
        if (kt + 1 < NT) {
            int k0 = (kt + 1) << 5;
            int nb = (kt + 1) & 1;
            cp16(s2u(smA[nb] + lr0 * PITCH + lc0 * 16),
                 A + (size_t)(row0 + lr0) * K + k0 + lc0 * 8, p0);
            cp16(s2u(smA[nb] + lr1 * PITCH + lc1 * 16),
                 A + (size_t)(row0 + lr1) * K + k0 + lc1 * 8, p1);
            cp16(s2u(smB[nb] + lr0 * PITCH + lc0 * 16),
                 Wb + (size_t)lr0 * ldw + k0 + lc0 * 8, true);
            cp16(s2u(smB[nb] + lr1 * PITCH + lc1 * 16),
                 Wb + (size_t)lr1 * ldw + k0 + lc1 * 8, true);
            CP_COMMIT();
            CP_WAIT1();
        } else {
            CP_WAIT0();
        }
        __syncthreads();

        const unsigned char* Ab = smA[kt & 1];
        const unsigned char* Bb = smB[kt & 1];
        #pragma unroll
        for (int ks = 0; ks < 2; ks++) {
            const int q0 = ks * 8 + (lane & 3);
            unsigned af[2][4];
            #pragma unroll
            for (int mi = 0; mi < 2; mi++) {
                int r = warpM * 32 + mi * 16 + (lane >> 2);
                af[mi][0] = *(const unsigned*)(Ab + r * PITCH + q0 * 4);
                af[mi][1] = *(const unsigned*)(Ab + (r + 8) * PITCH + q0 * 4);
                af[mi][2] = *(const unsigned*)(Ab + r * PITCH + (q0 + 4) * 4);
                af[mi][3] = *(const unsigned*)(Ab + (r + 8) * PITCH + (q0 + 4) * 4);
            }
            #pragma unroll
            for (int ni = 0; ni < 8; ni++) {
                int n = warpN * 64 + ni * 8 + (lane >> 2);
                unsigned b0 = *(const unsigned*)(Bb + n * PITCH + q0 * 4);
                unsigned b1 = *(const unsigned*)(Bb + n * PITCH + (q0 + 4) * 4);
                mma_bf16(acc[0][ni], af[0], b0, b1);
                mma_bf16(acc[1][ni], af[1], b0, b1);
            }
        }
        __syncthreads();
    }

    #pragma unroll
    for (int mi = 0; mi < 2; mi++) {
        int rbase = row0 + warpM * 32 + mi * 16 + (lane >> 2);
        #pragma unroll
        for (int ni = 0; ni < 8; ni++) {
            int col = warpN * 64 + ni * 8 + 2 * (lane & 3);
            if (rbase < NNODES)
                *(__half2*)(C + (size_t)rbase * NHID + col) =
                    __floats2half2_rn(acc[mi][ni][0], acc[mi][ni][1]);
            if (rbase + 8 < NNODES)
                *(__half2*)(C + (size_t)(rbase + 8) * NHID + col) =
                    __floats2half2_rn(acc[mi][ni][2], acc[mi][ni][3]);
        }
    }
}

// ---------------- SpMM + epilogue: h = relu(s + (A@z)/(deg+1)) -> bf16 ----------------
__global__ __launch_bounds__(256) void k_spmm(const __half* __restrict__ zh,
                                              const __half* __restrict__ sh,
                                              const int* __restrict__ rp,
                                              const int* __restrict__ col,
                                              __nv_bfloat16* __restrict__ hb,
                                              int nbase, int nend) {
    int lane = threadIdx.x & 31;
    int n    = nbase + ((blockIdx.x * 256 + threadIdx.x) >> 5);
    if (n >= nend) return;
    int e = rp[n], end = rp[n + 1];
    int deg = end - e;
    float ax = 0.f, ay = 0.f, az = 0.f, aw = 0.f;
    for (; e + 2 <= end; e += 2) {
        int c0 = col[e], c1 = col[e + 1];
        uint2 u0 = *(const uint2*)(zh + (size_t)c0 * NHID + lane * 4);
        uint2 u1 = *(const uint2*)(zh + (size_t)c1 * NHID + lane * 4);
        float2 p0 = __half22float2(*(__half2*)&u0.x);
        float2 p1 = __half22float2(*(__half2*)&u0.y);
        float2 q0 = __half22float2(*(__half2*)&u1.x);
        float2 q1 = __half22float2(*(__half2*)&u1.y);
        ax += p0.x + q0.x; ay += p0.y + q0.y;
        az += p1.x + q1.x; aw += p1.y + q1.y;
    }
    if (e < end) {
        int c0 = col[e];
        uint2 u0 = *(const uint2*)(zh + (size_t)c0 * NHID + lane * 4);
        float2 p0 = __half22float2(*(__half2*)&u0.x);
        float2 p1 = __half22float2(*(__half2*)&u0.y);
        ax += p0.x; ay += p0.y; az += p1.x; aw += p1.y;
    }
    float inv = 1.0f / (1.0f + (float)deg);
    uint2 su = *(const uint2*)(sh + (size_t)n * NHID + lane * 4);
    float2 s0 = __half22float2(*(__half2*)&su.x);
    float2 s1 = __half22float2(*(__half2*)&su.y);
    float ox = fmaxf(fmaf(ax, inv, s0.x), 0.f);
    float oy = fmaxf(fmaf(ay, inv, s0.y), 0.f);
    float oz = fmaxf(fmaf(az, inv, s1.x), 0.f);
    float ow = fmaxf(fmaf(aw, inv, s1.y), 0.f);
    *(uint2*)(hb + (size_t)n * NHID + lane * 4) =
        make_uint2(pack_bf16x2(ox, oy), pack_bf16x2(oz, ow));
}

// ---------------- MLP + log_softmax (tf32 MMA; A from bf16 h) ----------------
__global__ __launch_bounds__(128) void k_mlp_tc(const __nv_bfloat16* __restrict__ hb,
                                                const float* __restrict__ Wm,
                                                const float* __restrict__ b,
                                                float* __restrict__ out, int rowbase) {
    __shared__ unsigned As[32][132];
    __shared__ unsigned Bsm[NCLASS][132];
    __shared__ float    Ls[128][41];
    __shared__ float    bs[NCLASS];

    const int tid = threadIdx.x, lane = tid & 31, wid = tid >> 5;
    const int row0 = rowbase + blockIdx.x * 128;

    for (int i = tid; i < NCLASS * NHID; i += 128)
        Bsm[i >> 7][i & 127] = f2tf32(Wm[i]);
    if (tid < NCLASS) bs[tid] = b[tid];

    float acc[2][5][4];
    #pragma unroll
    for (int mi = 0; mi < 2; mi++)
        #pragma unroll
        for (int ni = 0; ni < 5; ni++)
            #pragma unroll
            for (int q = 0; q < 4; q++) acc[mi][ni][q] = 0.f;

    for (int k0 = 0; k0 < NHID; k0 += 32) {
        #pragma unroll
        for (int j = 0; j < 8; j++) {
            int i  = tid + j * 128;
            int r  = i >> 3;
            int c4 = (i & 7) * 4;
            uint2 u = make_uint2(0u, 0u);
            if (row0 + r < NNODES)
                u = *(const uint2*)(hb + (size_t)(row0 + r) * NHID + k0 + c4);
            As[c4 + 0][r] = u.x << 16;
            As[c4 + 1][r] = u.x & 0xffff0000u;
            As[c4 + 2][r] = u.y << 16;
            As[c4 + 3][r] = u.y & 0xffff0000u;
        }
        __syncthreads();

        #pragma unroll
        for (int kk = 0; kk < 32; kk += 8) {
            const int kc = kk + (lane & 3);
            unsigned af[2][4];
            #pragma unroll
            for (int mi = 0; mi < 2; mi++) {
                int r = wid * 32 + mi * 16 + (lane >> 2);
                af[mi][0] = As[kc][r];
                af[mi][1] = As[kc][r + 8];
                af[mi][2] = As[kc + 4][r];
                af[mi][3] = As[kc + 4][r + 8];
            }
            #pragma unroll
            for (int ni = 0; ni < 5; ni++) {
                int n = ni * 8 + (lane >> 2);
                unsigned b0 = Bsm[n][k0 + kc];
                unsigned b1 = Bsm[n][k0 + kc + 4];
                mma_tf32(acc[0][ni], af[0], b0, b1);
                mma_tf32(acc[1][ni], af[1], b0, b1);
            }
        }
        __syncthreads();
    }

    #pragma unroll
    for (int mi = 0; mi < 2; mi++) {
        int r = wid * 32 + mi * 16 + (lane >> 2);
        #pragma unroll
        for (int ni = 0; ni < 5; ni++) {
            int c = ni * 8 + 2 * (lane & 3);
            Ls[r][c]         = acc[mi][ni][0];
            Ls[r][c + 1]     = acc[mi][ni][1];
            Ls[r + 8][c]     = acc[mi][ni][2];
            Ls[r + 8][c + 1] = acc[mi][ni][3];
        }
    }
    __syncthreads();

    int gr = row0 + tid;
    if (gr >= NNODES) return;
    float l[NCLASS];
    float m = -INFINITY;
    #pragma unroll
    for (int c = 0; c < NCLASS; c++) {
        l[c] = Ls[tid][c] + bs[c];
        m = fmaxf(m, l[c]);
    }
    float se = 0.f;
    #pragma unroll
    for (int c = 0; c < NCLASS; c++) se += expf(l[c] - m);
    float lse = m + logf(se);
    float* op = out + (size_t)gr * NCLASS;
    #pragma unroll
    for (int c = 0; c < NCLASS; c += 4)
        *(float4*)(op + c) = make_float4(l[c] - lse, l[c + 1] - lse,
                                         l[c + 2] - lse, l[c + 3] - lse);
}

// ---------------- launch ----------------
extern "C" void kernel_launch(void* const* d_in, const int* in_sizes, int n_in,
                              void* d_out, int out_size) {
    const float* x    = (const float*)d_in[0];
    const float* W1   = (const float*)d_in[1];
    const float* W2   = (const float*)d_in[2];
    const float* mW   = (const float*)d_in[3];
    const float* mb   = (const float*)d_in[4];
    const int*   rows = (const int*)d_in[5];
    const int*   cols = (const int*)d_in[6];
    float*       out  = (float*)d_out;

    __half *p_sa, *p_za, *p_sb, *p_zb;
    __nv_bfloat16 *p_hb, *p_xb, *p_w1b, *p_w2b;
    int *p_deg, *p_rp, *p_cur, *p_col;
    cudaGetSymbolAddress((void**)&p_sa,  g_sa);
    cudaGetSymbolAddress((void**)&p_za,  g_za);
    cudaGetSymbolAddress((void**)&p_sb,  g_sb);
    cudaGetSymbolAddress((void**)&p_zb,  g_zb);
    cudaGetSymbolAddress((void**)&p_hb,  g_hb);
    cudaGetSymbolAddress((void**)&p_xb,  g_xb);
    cudaGetSymbolAddress((void**)&p_w1b, g_w1b);
    cudaGetSymbolAddress((void**)&p_w2b, g_w2b);
    cudaGetSymbolAddress((void**)&p_deg, g_deg);
    cudaGetSymbolAddress((void**)&p_rp,  g_rowptr);
    cudaGetSymbolAddress((void**)&p_cur, g_cursor);
    cudaGetSymbolAddress((void**)&p_col, g_col);

    static cudaStream_t s_side = nullptr;
    static cudaEvent_t ev_fork, ev_join, eS1[4], eG2, eS2[4], eDone;
    if (s_side == nullptr) {
        cudaStreamCreate(&s_side);
        cudaEventCreateWithFlags(&ev_fork, cudaEventDisableTiming);
        cudaEventCreateWithFlags(&ev_join, cudaEventDisableTiming);
        cudaEventCreateWithFlags(&eG2,     cudaEventDisableTiming);
        cudaEventCreateWithFlags(&eDone,   cudaEventDisableTiming);
        for (int i = 0; i < 4; i++) {
            cudaEventCreateWithFlags(&eS1[i], cudaEventDisableTiming);
            cudaEventCreateWithFlags(&eS2[i], cudaEventDisableTiming);
        }
    }

    static const int CB[5] = {0, 25088, 50176, 75264, 100000};

    const int GB_E4 = (NEDGES / 4 + 255) / 256;
    const dim3 GB_G1((NNODES + 127) / 128, 2);

    // ---- fork: CSR build on side stream ----
    cudaEventRecord(ev_fork, 0);
    cudaStreamWaitEvent(s_side, ev_fork, 0);
    cudaMemsetAsync(p_deg, 0, NNODES * sizeof(int), s_side);
    k_count<<<GB_E4, 256, 0, s_side>>>(rows, p_deg);
    k_scan<<<1, 1024, 0, s_side>>>(p_deg, p_rp, p_cur);
    k_fill<<<GB_E4, 256, 0, s_side>>>(rows, cols, p_cur, p_col);
    cudaEventRecord(ev_join, s_side);

    // ---- main: cvt + full layer-1 GEMM ----
    int n4x  = NNODES * NFEAT / 4;
    int n4w1 = NHID * 2 * NFEAT / 4;
    int n4w2 = NHID * 2 * NHID / 4;
    k_cvt<<<(n4w1 + 255) / 256, 256>>>(W1, p_w1b, n4w1);
    k_cvt<<<(n4w2 + 255) / 256, 256>>>(W2, p_w2b, n4w2);
    k_cvt<<<(n4x + 255) / 256, 256>>>(x,  p_xb,  n4x);
    k_gemm_bf16<<<GB_G1, 256>>>(p_xb, NFEAT, p_w1b, p_sa, p_za, 0);

    cudaStreamWaitEvent(0, ev_join, 0);

    // ---- SpMM1 chunks on main; GEMM2 chunks trail on side ----
    for (int i = 0; i < 4; i++) {
        int len = CB[i + 1] - CB[i];
        k_spmm<<<(len * 32 + 255) / 256, 256>>>(p_za, p_sa, p_rp, p_col, p_hb,
                                                CB[i], CB[i + 1]);
        cudaEventRecord(eS1[i], 0);
        cudaStreamWaitEvent(s_side, eS1[i], 0);
        dim3 g((len + 127) / 128, 2);
        k_gemm_bf16<<<g, 256, 0, s_side>>>(p_hb, NHID, p_w2b, p_sb, p_zb, CB[i]);
    }
    cudaEventRecord(eG2, s_side);
    cudaStreamWaitEvent(0, eG2, 0);

    // ---- SpMM2 chunks on main; MLP chunks trail on side ----
    for (int i = 0; i < 4; i++) {
        int len = CB[i + 1] - CB[i];
        k_spmm<<<(len * 32 + 255) / 256, 256>>>(p_zb, p_sb, p_rp, p_col, p_hb,
                                                CB[i], CB[i + 1]);
        cudaEventRecord(eS2[i], 0);
        cudaStreamWaitEvent(s_side, eS2[i], 0);
        k_mlp_tc<<<(len + 127) / 128, 128, 0, s_side>>>(p_hb, mW, mb, out, CB[i]);
    }
    cudaEventRecord(eDone, s_side);
    cudaStreamWaitEvent(0, eDone, 0);
}

// round 10
// speedup vs baseline: 1.0749x; 1.0749x over previous
#include <cuda_runtime.h>
#include <cuda_fp16.h>
#include <cuda_bf16.h>
#include <math.h>

#define NNODES 100000
#define NEDGES 3200000
#define NFEAT  256
#define NHID   128
#define NCLASS 40

// ---------------- scratch (static device globals; no allocs) ----------------
__device__ __half         g_sh[(size_t)NNODES * NHID];   // self proj fp16
__device__ __half         g_zh[(size_t)NNODES * NHID];   // neigh proj fp16
__device__ __nv_bfloat16  g_hb[(size_t)NNODES * NHID];   // layer output bf16
__device__ __nv_bfloat16  g_xb[(size_t)NNODES * NFEAT];  // x in bf16
__device__ __nv_bfloat16  g_w1b[NHID * 2 * NFEAT];
__device__ __nv_bfloat16  g_w2b[NHID * 2 * NHID];
__device__ int            g_deg[NNODES];
__device__ int            g_rowptr[NNODES + 1];
__device__ int            g_cursor[NNODES];
__device__ int            g_col[NEDGES];

// ---------------- helpers ----------------
__device__ __forceinline__ unsigned pack_bf16x2(float lo, float hi) {
    unsigned u;
    asm("cvt.rn.bf16x2.f32 %0, %1, %2;" : "=r"(u) : "f"(hi), "f"(lo));
    return u;
}
__device__ __forceinline__ unsigned f2tf32(float v) {
    unsigned u;
    asm("cvt.rna.tf32.f32 %0, %1;" : "=r"(u) : "f"(v));
    return u;
}
__device__ __forceinline__ void mma_bf16(float* c, const unsigned* a,
                                         unsigned b0, unsigned b1) {
    asm volatile(
        "mma.sync.aligned.m16n8k16.row.col.f32.bf16.bf16.f32 "
        "{%0,%1,%2,%3}, {%4,%5,%6,%7}, {%8,%9}, {%0,%1,%2,%3};"
        : "+f"(c[0]), "+f"(c[1]), "+f"(c[2]), "+f"(c[3])
        : "r"(a[0]), "r"(a[1]), "r"(a[2]), "r"(a[3]), "r"(b0), "r"(b1));
}
__device__ __forceinline__ void mma_tf32(float* c, const unsigned* a,
                                         unsigned b0, unsigned b1) {
    asm volatile(
        "mma.sync.aligned.m16n8k8.row.col.f32.tf32.tf32.f32 "
        "{%0,%1,%2,%3}, {%4,%5,%6,%7}, {%8,%9}, {%0,%1,%2,%3};"
        : "+f"(c[0]), "+f"(c[1]), "+f"(c[2]), "+f"(c[3])
        : "r"(a[0]), "r"(a[1]), "r"(a[2]), "r"(a[3]), "r"(b0), "r"(b1));
}
__device__ __forceinline__ unsigned s2u(const void* p) {
    return (unsigned)__cvta_generic_to_shared(p);
}
__device__ __forceinline__ void cp16(unsigned dst, const void* src, bool pred) {
    int sz = pred ? 16 : 0;
    asm volatile("cp.async.cg.shared.global [%0], [%1], 16, %2;"
                 :: "r"(dst), "l"(src), "r"(sz));
}
#define CP_COMMIT() asm volatile("cp.async.commit_group;")
#define CP_WAIT1()  asm volatile("cp.async.wait_group 1;")
#define CP_WAIT0()  asm volatile("cp.async.wait_group 0;")

// ---------------- fp32 -> bf16 convert ----------------
__global__ void k_cvt(const float* __restrict__ in, __nv_bfloat16* __restrict__ out,
                      int n4) {
    int i = blockIdx.x * blockDim.x + threadIdx.x;
    if (i < n4) {
        float4 v = ((const float4*)in)[i];
        ((uint2*)out)[i] = make_uint2(pack_bf16x2(v.x, v.y), pack_bf16x2(v.z, v.w));
    }
}

// ---------------- CSR build (4 edges / thread) ----------------
__global__ void k_count(const int* __restrict__ rows, int* __restrict__ deg) {
    int i = blockIdx.x * blockDim.x + threadIdx.x;
    if (i < NEDGES / 4) {
        int4 r = ((const int4*)rows)[i];
        atomicAdd(&deg[r.x], 1);
        atomicAdd(&deg[r.y], 1);
        atomicAdd(&deg[r.z], 1);
        atomicAdd(&deg[r.w], 1);
    }
}

__global__ void k_scan(const int* __restrict__ deg, int* __restrict__ rp,
                       int* __restrict__ cur) {
    __shared__ int wsum[32];
    __shared__ int carry;
    int tid = threadIdx.x, lane = tid & 31, wid = tid >> 5;
    if (tid == 0) carry = 0;
    __syncthreads();
    for (int base = 0; base < NNODES; base += 1024) {
        int i = base + tid;
        int v = (i < NNODES) ? deg[i] : 0;
        int x = v;
        #pragma unroll
        for (int d = 1; d < 32; d <<= 1) {
            int y = __shfl_up_sync(0xffffffffu, x, d);
            if (lane >= d) x += y;
        }
        if (lane == 31) wsum[wid] = x;
        __syncthreads();
        if (wid == 0) {
            int s = wsum[lane];
            #pragma unroll
            for (int d = 1; d < 32; d <<= 1) {
                int y = __shfl_up_sync(0xffffffffu, s, d);
                if (lane >= d) s += y;
            }
            wsum[lane] = s;
        }
        __syncthreads();
        int off  = carry + (wid ? wsum[wid - 1] : 0);
        int excl = off + x - v;
        if (i < NNODES) { rp[i] = excl; cur[i] = excl; }
        int tot = wsum[31];
        __syncthreads();
        if (tid == 0) carry += tot;
        __syncthreads();
    }
    if (tid == 0) rp[NNODES] = carry;
}

__global__ void k_fill(const int* __restrict__ rows, const int* __restrict__ cols,
                       int* __restrict__ cur, int* __restrict__ col) {
    int i = blockIdx.x * blockDim.x + threadIdx.x;
    if (i < NEDGES / 4) {
        int4 r = ((const int4*)rows)[i];
        int4 c = ((const int4*)cols)[i];
        col[atomicAdd(&cur[r.x], 1)] = c.x;
        col[atomicAdd(&cur[r.y], 1)] = c.y;
        col[atomicAdd(&cur[r.z], 1)] = c.z;
        col[atomicAdd(&cur[r.w], 1)] = c.w;
    }
}

// ---------------- pipelined bf16 GEMM (outputs fp16: s | z) ----------------
#define PITCH 80
__global__ __launch_bounds__(256) void k_gemm_bf16(
    const __nv_bfloat16* __restrict__ A, int K,
    const __nv_bfloat16* __restrict__ W,
    __half* __restrict__ Csh, __half* __restrict__ Czh)
{
    __shared__ __align__(16) unsigned char smA[2][128 * PITCH];
    __shared__ __align__(16) unsigned char smB[2][128 * PITCH];
    const int tid = threadIdx.x, lane = tid & 31, wid = tid >> 5;
    const int warpM = wid & 3, warpN = wid >> 2;
    const int row0 = blockIdx.x * 128;
    const int ldw = 2 * K;
    const __nv_bfloat16* Wb = W + (size_t)blockIdx.y * K;
    __half* C = blockIdx.y ? Czh : Csh;
    const int NT = K >> 5;

    const int lr0 = tid >> 2, lc0 = tid & 3;
    const int lr1 = (tid + 256) >> 2, lc1 = lc0;
    const bool p0 = (row0 + lr0) < NNODES;
    const bool p1 = (row0 + lr1) < NNODES;

    float acc[2][8][4];
    #pragma unroll
    for (int mi = 0; mi < 2; mi++)
        #pragma unroll
        for (int ni = 0; ni < 8; ni++)
            #pragma unroll
            for (int q = 0; q < 4; q++) acc[mi][ni][q] = 0.f;

    {
        cp16(s2u(smA[0] + lr0 * PITCH + lc0 * 16),
             A + (size_t)(row0 + lr0) * K + lc0 * 8, p0);
        cp16(s2u(smA[0] + lr1 * PITCH + lc1 * 16),
             A + (size_t)(row0 + lr1) * K + lc1 * 8, p1);
        cp16(s2u(smB[0] + lr0 * PITCH + lc0 * 16),
             Wb + (size_t)lr0 * ldw + lc0 * 8, true);
        cp16(s2u(smB[0] + lr1 * PITCH + lc1 * 16),
             Wb + (size_t)lr1 * ldw + lc1 * 8, true);
        CP_COMMIT();
    }

    for (int kt = 0; kt < NT; kt++) {
        if (kt + 1 < NT) {
            int k0 = (kt + 1) << 5;
            int nb = (kt + 1) & 1;
            cp16(s2u(smA[nb] + lr0 * PITCH + lc0 * 16),
                 A + (size_t)(row0 + lr0) * K + k0 + lc0 * 8, p0);
            cp16(s2u(smA[nb] + lr1 * PITCH + lc1 * 16),
                 A + (size_t)(row0 + lr1) * K + k0 + lc1 * 8, p1);
            cp16(s2u(smB[nb] + lr0 * PITCH + lc0 * 16),
                 Wb + (size_t)lr0 * ldw + k0 + lc0 * 8, true);
            cp16(s2u(smB[nb] + lr1 * PITCH + lc1 * 16),
                 Wb + (size_t)lr1 * ldw + k0 + lc1 * 8, true);
            CP_COMMIT();
            CP_WAIT1();
        } else {
            CP_WAIT0();
        }
        __syncthreads();

        const unsigned char* Ab = smA[kt & 1];
        const unsigned char* Bb = smB[kt & 1];
        #pragma unroll
        for (int ks = 0; ks < 2; ks++) {
            const int q0 = ks * 8 + (lane & 3);
            unsigned af[2][4];
            #pragma unroll
            for (int mi = 0; mi < 2; mi++) {
                int r = warpM * 32 + mi * 16 + (lane >> 2);
                af[mi][0] = *(const unsigned*)(Ab + r * PITCH + q0 * 4);
                af[mi][1] = *(const unsigned*)(Ab + (r + 8) * PITCH + q0 * 4);
                af[mi][2] = *(const unsigned*)(Ab + r * PITCH + (q0 + 4) * 4);
                af[mi][3] = *(const unsigned*)(Ab + (r + 8) * PITCH + (q0 + 4) * 4);
            }
            #pragma unroll
            for (int ni = 0; ni < 8; ni++) {
                int n = warpN * 64 + ni * 8 + (lane >> 2);
                unsigned b0 = *(const unsigned*)(Bb + n * PITCH + q0 * 4);
                unsigned b1 = *(const unsigned*)(Bb + n * PITCH + (q0 + 4) * 4);
                mma_bf16(acc[0][ni], af[0], b0, b1);
                mma_bf16(acc[1][ni], af[1], b0, b1);
            }
        }
        __syncthreads();
    }

    #pragma unroll
    for (int mi = 0; mi < 2; mi++) {
        int rbase = row0 + warpM * 32 + mi * 16 + (lane >> 2);
        #pragma unroll
        for (int ni = 0; ni < 8; ni++) {
            int col = warpN * 64 + ni * 8 + 2 * (lane & 3);
            if (rbase < NNODES)
                *(__half2*)(C + (size_t)rbase * NHID + col) =
                    __floats2half2_rn(acc[mi][ni][0], acc[mi][ni][1]);
            if (rbase + 8 < NNODES)
                *(__half2*)(C + (size_t)(rbase + 8) * NHID + col) =
                    __floats2half2_rn(acc[mi][ni][2], acc[mi][ni][3]);
        }
    }
}

// ---------------- SpMM: h = relu(s + (A@z)/(deg+1)), 4-way MLP ----------------
__global__ __launch_bounds__(256) void k_spmm(const __half* __restrict__ zh,
                                              const __half* __restrict__ sh,
                                              const int* __restrict__ rp,
                                              const int* __restrict__ col,
                                              __nv_bfloat16* __restrict__ hb) {
    int lane = threadIdx.x & 31;
    int n    = (blockIdx.x * 256 + threadIdx.x) >> 5;
    if (n >= NNODES) return;
    int e = rp[n], end = rp[n + 1];
    int deg = end - e;
    float ax = 0.f, ay = 0.f, az = 0.f, aw = 0.f;
    for (; e + 4 <= end; e += 4) {
        int c0 = col[e], c1 = col[e + 1], c2 = col[e + 2], c3 = col[e + 3];
        uint2 u0 = *(const uint2*)(zh + (size_t)c0 * NHID + lane * 4);
        uint2 u1 = *(const uint2*)(zh + (size_t)c1 * NHID + lane * 4);
        uint2 u2 = *(const uint2*)(zh + (size_t)c2 * NHID + lane * 4);
        uint2 u3 = *(const uint2*)(zh + (size_t)c3 * NHID + lane * 4);
        float2 a0 = __half22float2(*(__half2*)&u0.x), a1 = __half22float2(*(__half2*)&u0.y);
        float2 b0 = __half22float2(*(__half2*)&u1.x), b1 = __half22float2(*(__half2*)&u1.y);
        float2 d0 = __half22float2(*(__half2*)&u2.x), d1 = __half22float2(*(__half2*)&u2.y);
        float2 e0 = __half22float2(*(__half2*)&u3.x), e1 = __half22float2(*(__half2*)&u3.y);
        ax += (a0.x + b0.x) + (d0.x + e0.x);
        ay += (a0.y + b0.y) + (d0.y + e0.y);
        az += (a1.x + b1.x) + (d1.x + e1.x);
        aw += (a1.y + b1.y) + (d1.y + e1.y);
    }
    for (; e < end; e++) {
        int c0 = col[e];
        uint2 u0 = *(const uint2*)(zh + (size_t)c0 * NHID + lane * 4);
        float2 a0 = __half22float2(*(__half2*)&u0.x), a1 = __half22float2(*(__half2*)&u0.y);
        ax += a0.x; ay += a0.y; az += a1.x; aw += a1.y;
    }
    float inv = 1.0f / (1.0f + (float)deg);
    uint2 su = *(const uint2*)(sh + (size_t)n * NHID + lane * 4);
    float2 s0 = __half22float2(*(__half2*)&su.x);
    float2 s1 = __half22float2(*(__half2*)&su.y);
    float ox = fmaxf(fmaf(ax, inv, s0.x), 0.f);
    float oy = fmaxf(fmaf(ay, inv, s0.y), 0.f);
    float oz = fmaxf(fmaf(az, inv, s1.x), 0.f);
    float ow = fmaxf(fmaf(aw, inv, s1.y), 0.f);
    *(uint2*)(hb + (size_t)n * NHID + lane * 4) =
        make_uint2(pack_bf16x2(ox, oy), pack_bf16x2(oz, ow));
}

// ---------------- MLP + log_softmax (tf32 MMA; A from bf16 h) ----------------
__global__ __launch_bounds__(128) void k_mlp_tc(const __nv_bfloat16* __restrict__ hb,
                                                const float* __restrict__ Wm,
                                                const float* __restrict__ b,
                                                float* __restrict__ out) {
    __shared__ unsigned As[32][132];
    __shared__ unsigned Bsm[NCLASS][132];
    __shared__ float    Ls[128][41];
    __shared__ float    bs[NCLASS];

    const int tid = threadIdx.x, lane = tid & 31, wid = tid >> 5;
    const int row0 = blockIdx.x * 128;

    for (int i = tid; i < NCLASS * NHID; i += 128)
        Bsm[i >> 7][i & 127] = f2tf32(Wm[i]);
    if (tid < NCLASS) bs[tid] = b[tid];

    float acc[2][5][4];
    #pragma unroll
    for (int mi = 0; mi < 2; mi++)
        #pragma unroll
        for (int ni = 0; ni < 5; ni++)
            #pragma unroll
            for (int q = 0; q < 4; q++) acc[mi][ni][q] = 0.f;

    for (int k0 = 0; k0 < NHID; k0 += 32) {
        #pragma unroll
        for (int j = 0; j < 8; j++) {
            int i  = tid + j * 128;
            int r  = i >> 3;
            int c4 = (i & 7) * 4;
            uint2 u = make_uint2(0u, 0u);
            if (row0 + r < NNODES)
                u = *(const uint2*)(hb + (size_t)(row0 + r) * NHID + k0 + c4);
            As[c4 + 0][r] = u.x << 16;
            As[c4 + 1][r] = u.x & 0xffff0000u;
            As[c4 + 2][r] = u.y << 16;
            As[c4 + 3][r] = u.y & 0xffff0000u;
        }
        __syncthreads();

        #pragma unroll
        for (int kk = 0; kk < 32; kk += 8) {
            const int kc = kk + (lane & 3);
            unsigned af[2][4];
            #pragma unroll
            for (int mi = 0; mi < 2; mi++) {
                int r = wid * 32 + mi * 16 + (lane >> 2);
                af[mi][0] = As[kc][r];
                af[mi][1] = As[kc][r + 8];
                af[mi][2] = As[kc + 4][r];
                af[mi][3] = As[kc + 4][r + 8];
            }
            #pragma unroll
            for (int ni = 0; ni < 5; ni++) {
                int n = ni * 8 + (lane >> 2);
                unsigned b0 = Bsm[n][k0 + kc];
                unsigned b1 = Bsm[n][k0 + kc + 4];
                mma_tf32(acc[0][ni], af[0], b0, b1);
                mma_tf32(acc[1][ni], af[1], b0, b1);
            }
        }
        __syncthreads();
    }

    #pragma unroll
    for (int mi = 0; mi < 2; mi++) {
        int r = wid * 32 + mi * 16 + (lane >> 2);
        #pragma unroll
        for (int ni = 0; ni < 5; ni++) {
            int c = ni * 8 + 2 * (lane & 3);
            Ls[r][c]         = acc[mi][ni][0];
            Ls[r][c + 1]     = acc[mi][ni][1];
            Ls[r + 8][c]     = acc[mi][ni][2];
            Ls[r + 8][c + 1] = acc[mi][ni][3];
        }
    }
    __syncthreads();

    int gr = row0 + tid;
    if (gr >= NNODES) return;
    float l[NCLASS];
    float m = -INFINITY;
    #pragma unroll
    for (int c = 0; c < NCLASS; c++) {
        l[c] = Ls[tid][c] + bs[c];
        m = fmaxf(m, l[c]);
    }
    float se = 0.f;
    #pragma unroll
    for (int c = 0; c < NCLASS; c++) se += expf(l[c] - m);
    float lse = m + logf(se);
    float* op = out + (size_t)gr * NCLASS;
    #pragma unroll
    for (int c = 0; c < NCLASS; c += 4)
        *(float4*)(op + c) = make_float4(l[c] - lse, l[c + 1] - lse,
                                         l[c + 2] - lse, l[c + 3] - lse);
}

// ---------------- launch ----------------
extern "C" void kernel_launch(void* const* d_in, const int* in_sizes, int n_in,
                              void* d_out, int out_size) {
    const float* x    = (const float*)d_in[0];
    const float* W1   = (const float*)d_in[1];
    const float* W2   = (const float*)d_in[2];
    const float* mW   = (const float*)d_in[3];
    const float* mb   = (const float*)d_in[4];
    const int*   rows = (const int*)d_in[5];
    const int*   cols = (const int*)d_in[6];
    float*       out  = (float*)d_out;

    __half *p_sh, *p_zh;
    __nv_bfloat16 *p_hb, *p_xb, *p_w1b, *p_w2b;
    int *p_deg, *p_rp, *p_cur, *p_col;
    cudaGetSymbolAddress((void**)&p_sh,  g_sh);
    cudaGetSymbolAddress((void**)&p_zh,  g_zh);
    cudaGetSymbolAddress((void**)&p_hb,  g_hb);
    cudaGetSymbolAddress((void**)&p_xb,  g_xb);
    cudaGetSymbolAddress((void**)&p_w1b, g_w1b);
    cudaGetSymbolAddress((void**)&p_w2b, g_w2b);
    cudaGetSymbolAddress((void**)&p_deg, g_deg);
    cudaGetSymbolAddress((void**)&p_rp,  g_rowptr);
    cudaGetSymbolAddress((void**)&p_cur, g_cursor);
    cudaGetSymbolAddress((void**)&p_col, g_col);

    static cudaStream_t s_side = nullptr;
    static cudaEvent_t  ev_fork = nullptr, ev_join = nullptr;
    if (s_side == nullptr) {
        cudaStreamCreate(&s_side);
        cudaEventCreateWithFlags(&ev_fork, cudaEventDisableTiming);
        cudaEventCreateWithFlags(&ev_join, cudaEventDisableTiming);
    }

    const int GB_E4 = (NEDGES / 4 + 255) / 256;
    const int GB_W  = (NNODES * 32 + 255) / 256;
    const int GB_T  = (NNODES + 127) / 128;
    const dim3 GB_G(GB_T, 2);

    // ---- fork: CSR build on side stream, concurrent with cvt + GEMM1 ----
    cudaEventRecord(ev_fork, 0);
    cudaStreamWaitEvent(s_side, ev_fork, 0);
    cudaMemsetAsync(p_deg, 0, NNODES * sizeof(int), s_side);
    k_count<<<GB_E4, 256, 0, s_side>>>(rows, p_deg);
    k_scan<<<1, 1024, 0, s_side>>>(p_deg, p_rp, p_cur);
    k_fill<<<GB_E4, 256, 0, s_side>>>(rows, cols, p_cur, p_col);
    cudaEventRecord(ev_join, s_side);

    // ---- main: bf16 conversions + layer-1 GEMM ----
    int n4x  = NNODES * NFEAT / 4;
    int n4w1 = NHID * 2 * NFEAT / 4;
    int n4w2 = NHID * 2 * NHID / 4;
    k_cvt<<<(n4w1 + 255) / 256, 256>>>(W1, p_w1b, n4w1);
    k_cvt<<<(n4w2 + 255) / 256, 256>>>(W2, p_w2b, n4w2);
    k_cvt<<<(n4x + 255) / 256, 256>>>(x,  p_xb,  n4x);
    k_gemm_bf16<<<GB_G, 256>>>(p_xb, NFEAT, p_w1b, p_sh, p_zh);

    // ---- join: SpMM needs CSR + z + s ----
    cudaStreamWaitEvent(0, ev_join, 0);
    k_spmm<<<GB_W, 256>>>(p_zh, p_sh, p_rp, p_col, p_hb);

    // Layer 2
    k_gemm_bf16<<<GB_G, 256>>>(p_hb, NHID, p_w2b, p_sh, p_zh);
    k_spmm<<<GB_W, 256>>>(p_zh, p_sh, p_rp, p_col, p_hb);

    // MLP + log_softmax
    k_mlp_tc<<<GB_T, 128>>>(p_hb, mW, mb, out);
}